// round 2
// baseline (speedup 1.0000x reference)
#include <cuda_runtime.h>
#include <cuda_bf16.h>
#include <cstdint>

#define IN_DIM   128
#define H_DIM    256
#define M_DIM    32
#define K_TOT    384
#define TILE_M   128
#define TILE_N   128
#define KC       64
#define THREADS  256

// ---- SMEM layout (bytes): 4 operand tiles (128 rows x 128B) + m-gate tile ----
#define SM_AHI    0
#define SM_ALO    16384
#define SM_WHI    32768
#define SM_WLO    49152
#define SM_M      65536                 // 128 rows * 272B (padded) = 34816
#define SM_MSTRIDE 272
#define SM_TOTAL  (SM_M + 128*SM_MSTRIDE)   // 100352

static __device__ __forceinline__ uint32_t smem_u32(const void* p) {
    uint32_t a;
    asm("{ .reg .u64 t; cvta.to.shared.u64 t, %1; cvt.u32.u64 %0, t; }" : "=r"(a) : "l"(p));
    return a;
}

static __device__ __forceinline__ void ldsm4(uint32_t* r, uint32_t addr) {
    asm volatile("ldmatrix.sync.aligned.m8n8.x4.shared.b16 {%0,%1,%2,%3}, [%4];"
                 : "=r"(r[0]), "=r"(r[1]), "=r"(r[2]), "=r"(r[3]) : "r"(addr));
}

static __device__ __forceinline__ void mma_bf16(float* d, const uint32_t* a, const uint32_t* b) {
    asm volatile("mma.sync.aligned.m16n8k16.row.col.f32.bf16.bf16.f32 "
                 "{%0,%1,%2,%3}, {%4,%5,%6,%7}, {%8,%9}, {%0,%1,%2,%3};"
                 : "+f"(d[0]), "+f"(d[1]), "+f"(d[2]), "+f"(d[3])
                 : "r"(a[0]), "r"(a[1]), "r"(a[2]), "r"(a[3]), "r"(b[0]), "r"(b[1]));
}

// fp32 -> bf16 hi/lo split, 8B swizzled stores into two tiles
static __device__ __forceinline__ void cvt_store(char* sm, int hi_base, int lo_base,
                                                 uint32_t boff, float4 v) {
    __nv_bfloat16 h0 = __float2bfloat16(v.x);
    __nv_bfloat16 h1 = __float2bfloat16(v.y);
    __nv_bfloat16 h2 = __float2bfloat16(v.z);
    __nv_bfloat16 h3 = __float2bfloat16(v.w);
    __nv_bfloat16 l0 = __float2bfloat16(v.x - __bfloat162float(h0));
    __nv_bfloat16 l1 = __float2bfloat16(v.y - __bfloat162float(h1));
    __nv_bfloat16 l2 = __float2bfloat16(v.z - __bfloat162float(h2));
    __nv_bfloat16 l3 = __float2bfloat16(v.w - __bfloat162float(h3));
    uint32_t sw = boff ^ ((boff >> 3) & 0x70);
    uint2 hv, lv;
    hv.x = (uint32_t)__bfloat16_as_ushort(h0) | ((uint32_t)__bfloat16_as_ushort(h1) << 16);
    hv.y = (uint32_t)__bfloat16_as_ushort(h2) | ((uint32_t)__bfloat16_as_ushort(h3) << 16);
    lv.x = (uint32_t)__bfloat16_as_ushort(l0) | ((uint32_t)__bfloat16_as_ushort(l1) << 16);
    lv.y = (uint32_t)__bfloat16_as_ushort(l2) | ((uint32_t)__bfloat16_as_ushort(l3) << 16);
    *reinterpret_cast<uint2*>(sm + hi_base + sw) = hv;
    *reinterpret_cast<uint2*>(sm + lo_base + sw) = lv;
}

__global__ __launch_bounds__(THREADS, 2)
void rlstm_kernel(const float* __restrict__ inp, const float* __restrict__ media,
                  const float* __restrict__ h_t, const float* __restrict__ c_t,
                  const float* __restrict__ Wi, const float* __restrict__ bi,
                  const float* __restrict__ Wm, const float* __restrict__ bm,
                  float* __restrict__ out, int Btot) {
    extern __shared__ char sm[];
    const uint32_t sb = smem_u32(sm);
    const int tid = threadIdx.x;
    const int lid = tid & 31;
    const int wid = tid >> 5;
    const int wm = wid & 3;          // warp row (4 x 32 = 128 M)
    const int wn = wid >> 2;         // warp col (2 x 64 = 128 N)
    const int m0 = (blockIdx.x >> 1) * TILE_M;
    const int n0 = (blockIdx.x & 1) * TILE_N;

    // ---- per-lane ldmatrix address components ----
    const int a_row0 = wm * 32 + (lid & 15);          // + mblk*16
    const int a_kh   = lid >> 4;
    const int b_row0 = wn * 64 + (lid & 7) + ((lid >> 4) << 3);   // + p*16
    const int b_kh   = (lid >> 3) & 1;

    auto a_addr = [&](uint32_t base, int mblk, int ks) -> uint32_t {
        int row = a_row0 + mblk * 16;
        uint32_t c16 = (uint32_t)(ks * 2 + a_kh) ^ (uint32_t)(row & 7);
        return base + (uint32_t)row * 128u + (c16 << 4);
    };
    auto b_addr = [&](uint32_t base, int p, int ks) -> uint32_t {
        int row = b_row0 + p * 16;
        uint32_t c16 = (uint32_t)(ks * 2 + b_kh) ^ (uint32_t)(row & 7);
        return base + (uint32_t)row * 128u + (c16 << 4);
    };

    // run one K-chunk of MMAs: 3-way bf16 split, ksteps k-steps of 16
    auto run_chunk = [&](float (*d)[8][4], int ksteps) {
        const uint32_t bAH = sb + SM_AHI, bAL = sb + SM_ALO;
        const uint32_t bWH = sb + SM_WHI, bWL = sb + SM_WLO;
        for (int ks = 0; ks < ksteps; ks++) {
            uint32_t afh[2][4], afl[2][4], bf[8][2];
            #pragma unroll
            for (int mb = 0; mb < 2; mb++) {
                ldsm4(afh[mb], a_addr(bAH, mb, ks));
                ldsm4(afl[mb], a_addr(bAL, mb, ks));
            }
            #pragma unroll
            for (int p = 0; p < 4; p++) {
                uint32_t t4[4];
                ldsm4(t4, b_addr(bWH, p, ks));
                bf[2*p][0] = t4[0]; bf[2*p][1] = t4[1];
                bf[2*p+1][0] = t4[2]; bf[2*p+1][1] = t4[3];
            }
            #pragma unroll
            for (int mb = 0; mb < 2; mb++)
                #pragma unroll
                for (int nb = 0; nb < 8; nb++) {
                    mma_bf16(d[mb][nb], afh[mb], bf[nb]);
                    mma_bf16(d[mb][nb], afl[mb], bf[nb]);
                }
            #pragma unroll
            for (int p = 0; p < 4; p++) {
                uint32_t t4[4];
                ldsm4(t4, b_addr(bWL, p, ks));
                bf[2*p][0] = t4[0]; bf[2*p][1] = t4[1];
                bf[2*p+1][0] = t4[2]; bf[2*p+1][1] = t4[3];
            }
            #pragma unroll
            for (int mb = 0; mb < 2; mb++)
                #pragma unroll
                for (int nb = 0; nb < 8; nb++)
                    mma_bf16(d[mb][nb], afh[mb], bf[nb]);
        }
    };

    // ================= pass 1: media gate GEMM (K=32) =================
    {
        // load media tile (128 x 32) and Wm tile (128 x 32)
        #pragma unroll
        for (int it = 0; it < 4; it++) {
            int f = tid + it * THREADS;           // 0..1023
            int row = f >> 3;
            int c4  = (f & 7) << 2;
            float4 v  = *reinterpret_cast<const float4*>(media + (size_t)(m0 + row) * M_DIM + c4);
            float4 w  = *reinterpret_cast<const float4*>(Wm + (size_t)(n0 + row) * M_DIM + c4);
            cvt_store(sm, SM_AHI, SM_ALO, (uint32_t)(row * 128 + c4 * 2), v);
            cvt_store(sm, SM_WHI, SM_WLO, (uint32_t)(row * 128 + c4 * 2), w);
        }
        __syncthreads();

        float dm[2][8][4];
        #pragma unroll
        for (int mb = 0; mb < 2; mb++)
            #pragma unroll
            for (int nb = 0; nb < 8; nb++)
                #pragma unroll
                for (int j = 0; j < 4; j++) dm[mb][nb][j] = 0.f;

        run_chunk(dm, 2);   // K = 32

        // sigmoid + pack to u16 fixed point in SMEM
        #pragma unroll
        for (int mb = 0; mb < 2; mb++)
            #pragma unroll
            for (int nb = 0; nb < 8; nb++) {
                int colg = n0 + wn * 64 + nb * 8 + (lid & 3) * 2;
                float2 bmv = *reinterpret_cast<const float2*>(bm + colg);
                #pragma unroll
                for (int jh = 0; jh < 2; jh++) {
                    float x0 = dm[mb][nb][jh*2+0] + bmv.x;
                    float x1 = dm[mb][nb][jh*2+1] + bmv.y;
                    x0 = fminf(fmaxf(x0, -30.f), 30.f);
                    x1 = fminf(fmaxf(x1, -30.f), 30.f);
                    float g0 = __fdividef(1.f, 1.f + __expf(-x0));
                    float g1 = __fdividef(1.f, 1.f + __expf(-x1));
                    uint32_t q0 = __float2uint_rn(g0 * 65535.f);
                    uint32_t q1 = __float2uint_rn(g1 * 65535.f);
                    int rowl = wm * 32 + mb * 16 + (lid >> 2) + jh * 8;
                    int cp   = wn * 32 + nb * 4 + (lid & 3);
                    *reinterpret_cast<uint32_t*>(sm + SM_M + rowl * SM_MSTRIDE + cp * 4)
                        = q0 | (q1 << 16);
                }
            }
    }

    // ================= pass 2: main GEMM (K=384, 6 chunks) =================
    float d[2][8][4];
    #pragma unroll
    for (int mb = 0; mb < 2; mb++)
        #pragma unroll
        for (int nb = 0; nb < 8; nb++)
            #pragma unroll
            for (int j = 0; j < 4; j++) d[mb][nb][j] = 0.f;

    for (int ch = 0; ch < 6; ch++) {
        __syncthreads();        // previous consumers done (also covers media pass)
        int k0 = ch * KC;
        // A tile: combined[m0.., k0..k0+63]
        #pragma unroll
        for (int it = 0; it < 8; it++) {
            int f = tid + it * THREADS;       // 0..2047
            int row = f >> 4;
            int c4  = (f & 15) << 2;
            int kk  = k0 + c4;
            float4 v;
            if (kk < IN_DIM)
                v = *reinterpret_cast<const float4*>(inp + (size_t)(m0 + row) * IN_DIM + kk);
            else
                v = *reinterpret_cast<const float4*>(h_t + (size_t)(m0 + row) * H_DIM + (kk - IN_DIM));
            cvt_store(sm, SM_AHI, SM_ALO, (uint32_t)(row * 128 + c4 * 2), v);
        }
        // W tile: Wi[n0+row][k0..]
        #pragma unroll
        for (int it = 0; it < 8; it++) {
            int f = tid + it * THREADS;
            int row = f >> 4;
            int c4  = (f & 15) << 2;
            float4 w = *reinterpret_cast<const float4*>(Wi + (size_t)(n0 + row) * K_TOT + k0 + c4);
            cvt_store(sm, SM_WHI, SM_WLO, (uint32_t)(row * 128 + c4 * 2), w);
        }
        __syncthreads();
        run_chunk(d, 4);
    }

    // ================= epilogue =================
    const size_t BH = (size_t)Btot * H_DIM;
    #pragma unroll
    for (int mb = 0; mb < 2; mb++)
        #pragma unroll
        for (int nb = 0; nb < 8; nb++) {
            int colg = n0 + wn * 64 + nb * 8 + (lid & 3) * 2;
            float2 biv = *reinterpret_cast<const float2*>(bi + colg);
            #pragma unroll
            for (int jh = 0; jh < 2; jh++) {
                int rowl = wm * 32 + mb * 16 + (lid >> 2) + jh * 8;
                int rowg = m0 + rowl;
                int cp   = wn * 32 + nb * 4 + (lid & 3);
                uint32_t mq = *reinterpret_cast<const uint32_t*>(sm + SM_M + rowl * SM_MSTRIDE + cp * 4);
                float mgate0 = (float)(mq & 0xFFFF) * (1.f / 65535.f);
                float mgate1 = (float)(mq >> 16)    * (1.f / 65535.f);
                size_t o = (size_t)rowg * H_DIM + colg;
                float2 ct = *reinterpret_cast<const float2*>(c_t + o);

                float hv[2], cv[2];
                float gr[2] = { d[mb][nb][jh*2+0] + biv.x, d[mb][nb][jh*2+1] + biv.y };
                float ctv[2] = { ct.x, ct.y };
                float mg[2] = { mgate0, mgate1 };
                #pragma unroll
                for (int e = 0; e < 2; e++) {
                    float g = fminf(fmaxf(gr[e], -30.f), 30.f);
                    float ex = __expf(-g);
                    float gate = __fdividef(1.f, 1.f + ex);
                    float e2 = ex * ex;
                    float thg = __fdividef(1.f - e2, 1.f + e2);        // tanh(g)
                    float c = gate * (ctv[e] + thg);
                    float cc = fminf(fmaxf(c, -15.f), 15.f);
                    float ec = __expf(-2.f * cc);
                    float cr = __fdividef(1.f - ec, 1.f + ec);         // tanh(c)
                    float cf = c - cr + cr * mg[e];
                    float cfc = fminf(fmaxf(cf, -15.f), 15.f);
                    float ef = __expf(-2.f * cfc);
                    float thf = __fdividef(1.f - ef, 1.f + ef);        // tanh(c_f)
                    hv[e] = thf * gate;
                    cv[e] = c;
                }
                float2 hvv = make_float2(hv[0], hv[1]);
                float2 cvv = make_float2(cv[0], cv[1]);
                *reinterpret_cast<float2*>(out + o)          = hvv;
                *reinterpret_cast<float2*>(out + BH + o)     = hvv;
                *reinterpret_cast<float2*>(out + 2 * BH + o) = cvv;
            }
        }
}

extern "C" void kernel_launch(void* const* d_in, const int* in_sizes, int n_in,
                              void* d_out, int out_size) {
    const float* inp   = (const float*)d_in[0];
    const float* media = (const float*)d_in[1];
    const float* h_t   = (const float*)d_in[2];
    const float* c_t   = (const float*)d_in[3];
    const float* Wi    = (const float*)d_in[4];
    const float* bi    = (const float*)d_in[5];
    const float* Wm    = (const float*)d_in[6];
    const float* bm    = (const float*)d_in[7];
    int B = in_sizes[0] / IN_DIM;

    cudaFuncSetAttribute(rlstm_kernel, cudaFuncAttributeMaxDynamicSharedMemorySize, SM_TOTAL);
    dim3 grid((B / TILE_M) * 2);
    rlstm_kernel<<<grid, THREADS, SM_TOTAL>>>(inp, media, h_t, c_t, Wi, bi, Wm, bm,
                                              (float*)d_out, B);
}

// round 5
// speedup vs baseline: 1.0132x; 1.0132x over previous
#include <cuda_runtime.h>
#include <cuda_bf16.h>
#include <cstdint>

#define IN_DIM   128
#define H_DIM    256
#define M_DIM    32
#define K_TOT    384
#define TILE_M   128
#define TILE_N   128
#define KC       32
#define NCHUNK   12
#define THREADS  256

// ---- SMEM layout (byte offsets) ----
// Each buffer: A_hi | A_lo | W_hi | W_lo, each 128 rows x 64B (8KB) = 32KB
#define OFF_AHI  0
#define OFF_ALO  8192
#define OFF_WHI  16384
#define OFF_WLO  24576
#define SM_BUF0  0
#define SM_BUF1  32768
#define SM_M     65536
#define SM_MSTRIDE 272
#define SM_TOTAL (SM_M + TILE_M*SM_MSTRIDE)   // 100352

static __device__ __forceinline__ uint32_t smem_u32(const void* p) {
    uint32_t a;
    asm("{ .reg .u64 t; cvta.to.shared.u64 t, %1; cvt.u32.u64 %0, t; }" : "=r"(a) : "l"(p));
    return a;
}
static __device__ __forceinline__ void ldsm4(uint32_t* r, uint32_t addr) {
    asm volatile("ldmatrix.sync.aligned.m8n8.x4.shared.b16 {%0,%1,%2,%3}, [%4];"
                 : "=r"(r[0]), "=r"(r[1]), "=r"(r[2]), "=r"(r[3]) : "r"(addr));
}
static __device__ __forceinline__ void mma_bf16(float* d, const uint32_t* a, const uint32_t* b) {
    asm volatile("mma.sync.aligned.m16n8k16.row.col.f32.bf16.bf16.f32 "
                 "{%0,%1,%2,%3}, {%4,%5,%6,%7}, {%8,%9}, {%0,%1,%2,%3};"
                 : "+f"(d[0]), "+f"(d[1]), "+f"(d[2]), "+f"(d[3])
                 : "r"(a[0]), "r"(a[1]), "r"(a[2]), "r"(a[3]), "r"(b[0]), "r"(b[1]));
}

// fp32x4 -> packed bf16 hi (uint2) + lo residue (uint2)
static __device__ __forceinline__ void split4(float4 v, uint2& hv, uint2& lv) {
    __nv_bfloat162 h01 = __float22bfloat162_rn(make_float2(v.x, v.y));
    __nv_bfloat162 h23 = __float22bfloat162_rn(make_float2(v.z, v.w));
    uint32_t u01 = *reinterpret_cast<uint32_t*>(&h01);
    uint32_t u23 = *reinterpret_cast<uint32_t*>(&h23);
    float xh = __uint_as_float(u01 << 16);
    float yh = __uint_as_float(u01 & 0xFFFF0000u);
    float zh = __uint_as_float(u23 << 16);
    float wh = __uint_as_float(u23 & 0xFFFF0000u);
    __nv_bfloat162 l01 = __float22bfloat162_rn(make_float2(v.x - xh, v.y - yh));
    __nv_bfloat162 l23 = __float22bfloat162_rn(make_float2(v.z - zh, v.w - wh));
    hv.x = u01; hv.y = u23;
    lv.x = *reinterpret_cast<uint32_t*>(&l01);
    lv.y = *reinterpret_cast<uint32_t*>(&l23);
}

__global__ __launch_bounds__(THREADS, 2)
void rlstm_kernel(const float* __restrict__ inp, const float* __restrict__ media,
                  const float* __restrict__ h_t, const float* __restrict__ c_t,
                  const float* __restrict__ Wi, const float* __restrict__ bi,
                  const float* __restrict__ Wm, const float* __restrict__ bm,
                  float* __restrict__ out, int Btot) {
    extern __shared__ char sm[];
    const uint32_t sb = smem_u32(sm);
    const int tid = threadIdx.x;
    const int lid = tid & 31;
    const int wid = tid >> 5;
    const int wm = wid & 3;          // warp row (4 x 32 = 128 M)
    const int wn = wid >> 2;         // warp col (2 x 64 = 128 N)
    const int m0 = (int)(blockIdx.x >> 1) * TILE_M;
    const int n0 = (int)(blockIdx.x & 1) * TILE_N;

    // ldmatrix per-lane components
    const int a_row0 = wm * 32 + (lid & 15);
    const int a_kh   = lid >> 4;
    const int b_row0 = wn * 64 + (lid & 7) + ((lid >> 4) << 3);
    const int b_kh   = (lid >> 3) & 1;

    // per-thread loader coords: unit = 16B (4 fp32) of a 32-float row-chunk
    const int l_row = tid >> 3;            // +32 per iteration
    const int l_unit = tid & 7;
    const int l_k = l_unit * 4;

    float4 r[8];                           // prefetch: A in r[0..3], W in r[4..7]

    auto load_main = [&](int ch) {
        int kk = ch * KC + l_k;
        #pragma unroll
        for (int it = 0; it < 4; it++) {
            int row = l_row + it * 32;
            r[it] = (kk < IN_DIM)
                ? *reinterpret_cast<const float4*>(inp + (size_t)(m0 + row) * IN_DIM + kk)
                : *reinterpret_cast<const float4*>(h_t + (size_t)(m0 + row) * H_DIM + (kk - IN_DIM));
            r[4 + it] = *reinterpret_cast<const float4*>(Wi + (size_t)(n0 + row) * K_TOT + kk);
        }
    };
    auto load_media = [&]() {
        #pragma unroll
        for (int it = 0; it < 4; it++) {
            int row = l_row + it * 32;
            r[it]     = *reinterpret_cast<const float4*>(media + (size_t)(m0 + row) * M_DIM + l_k);
            r[4 + it] = *reinterpret_cast<const float4*>(Wm + (size_t)(n0 + row) * M_DIM + l_k);
        }
    };
    auto sts_all = [&](uint32_t buf) {
        #pragma unroll
        for (int it = 0; it < 4; it++) {
            int row = l_row + it * 32;
            uint32_t boff = (uint32_t)(row * 64 + l_unit * 8);
            uint32_t sw = boff ^ ((boff >> 3) & 0x30);   // XORs 16B-unit bits with row bits 1..2
            uint2 hv, lv;
            split4(r[it], hv, lv);
            *reinterpret_cast<uint2*>(sm + buf + OFF_AHI + sw) = hv;
            *reinterpret_cast<uint2*>(sm + buf + OFF_ALO + sw) = lv;
            split4(r[4 + it], hv, lv);
            *reinterpret_cast<uint2*>(sm + buf + OFF_WHI + sw) = hv;
            *reinterpret_cast<uint2*>(sm + buf + OFF_WLO + sw) = lv;
        }
    };

    float d[2][8][4];
    auto zero_d = [&]() {
        #pragma unroll
        for (int mb = 0; mb < 2; mb++)
            #pragma unroll
            for (int nb = 0; nb < 8; nb++)
                #pragma unroll
                for (int j = 0; j < 4; j++) d[mb][nb][j] = 0.f;
    };

    auto run_chunk = [&](uint32_t buf) {
        const uint32_t bAH = sb + buf + OFF_AHI, bAL = sb + buf + OFF_ALO;
        const uint32_t bWH = sb + buf + OFF_WHI, bWL = sb + buf + OFF_WLO;
        #pragma unroll
        for (int ks = 0; ks < 2; ks++) {
            uint32_t afh[2][4], afl[2][4];
            #pragma unroll
            for (int mb = 0; mb < 2; mb++) {
                int row = a_row0 + mb * 16;
                // read-side swizzle must match store: XOR with row bits 1..2
                uint32_t u = ((uint32_t)(ks * 2 + a_kh) ^ (uint32_t)((row >> 1) & 3)) << 4;
                ldsm4(afh[mb], bAH + (uint32_t)row * 64u + u);
                ldsm4(afl[mb], bAL + (uint32_t)row * 64u + u);
            }
            #pragma unroll
            for (int p = 0; p < 4; p++) {
                int row = b_row0 + p * 16;
                uint32_t u = ((uint32_t)(ks * 2 + b_kh) ^ (uint32_t)((row >> 1) & 3)) << 4;
                uint32_t t[4];
                ldsm4(t, bWH + (uint32_t)row * 64u + u);
                mma_bf16(d[0][2*p],   afh[0], t);     mma_bf16(d[0][2*p+1], afh[0], t + 2);
                mma_bf16(d[1][2*p],   afh[1], t);     mma_bf16(d[1][2*p+1], afh[1], t + 2);
                mma_bf16(d[0][2*p],   afl[0], t);     mma_bf16(d[0][2*p+1], afl[0], t + 2);
                mma_bf16(d[1][2*p],   afl[1], t);     mma_bf16(d[1][2*p+1], afl[1], t + 2);
            }
            #pragma unroll
            for (int p = 0; p < 4; p++) {
                int row = b_row0 + p * 16;
                uint32_t u = ((uint32_t)(ks * 2 + b_kh) ^ (uint32_t)((row >> 1) & 3)) << 4;
                uint32_t t[4];
                ldsm4(t, bWL + (uint32_t)row * 64u + u);
                mma_bf16(d[0][2*p],   afh[0], t);     mma_bf16(d[0][2*p+1], afh[0], t + 2);
                mma_bf16(d[1][2*p],   afh[1], t);     mma_bf16(d[1][2*p+1], afh[1], t + 2);
            }
        }
    };

    // ================= media prologue (chunk in buf0) =================
    load_media();
    sts_all(SM_BUF0);
    __syncthreads();
    zero_d();
    run_chunk(SM_BUF0);
    load_main(0);                 // prefetch main chunk 0 (hides DRAM latency behind sigmoid)

    // sigmoid(media GEMM + bm) -> u16 fixed point in m-tile (same-thread read later)
    #pragma unroll
    for (int mb = 0; mb < 2; mb++)
        #pragma unroll
        for (int nb = 0; nb < 8; nb++) {
            int colg = n0 + wn * 64 + nb * 8 + (lid & 3) * 2;
            float2 bmv = *reinterpret_cast<const float2*>(bm + colg);
            #pragma unroll
            for (int jh = 0; jh < 2; jh++) {
                float x0 = fminf(fmaxf(d[mb][nb][jh*2+0] + bmv.x, -30.f), 30.f);
                float x1 = fminf(fmaxf(d[mb][nb][jh*2+1] + bmv.y, -30.f), 30.f);
                float g0 = __fdividef(1.f, 1.f + __expf(-x0));
                float g1 = __fdividef(1.f, 1.f + __expf(-x1));
                uint32_t q0 = __float2uint_rn(g0 * 65535.f);
                uint32_t q1 = __float2uint_rn(g1 * 65535.f);
                int rowl = wm * 32 + mb * 16 + (lid >> 2) + jh * 8;
                int cp   = wn * 32 + nb * 4 + (lid & 3);
                *reinterpret_cast<uint32_t*>(sm + SM_M + rowl * SM_MSTRIDE + cp * 4)
                    = q0 | (q1 << 16);
            }
        }

    sts_all(SM_BUF1);             // chunk 0 -> buf1
    zero_d();
    __syncthreads();

    // ================= main pipeline: 12 chunks, double-buffered =================
    #pragma unroll 1
    for (int ch = 0; ch < NCHUNK; ch++) {
        uint32_t bufR = (ch & 1) ? SM_BUF0 : SM_BUF1;   // chunk ch lives here
        uint32_t bufW = (ch & 1) ? SM_BUF1 : SM_BUF0;   // chunk ch+1 goes here
        if (ch < NCHUNK - 1) load_main(ch + 1);         // LDG issues before MMAs
        run_chunk(bufR);
        if (ch < NCHUNK - 1) {
            sts_all(bufW);
            __syncthreads();
        }
    }

    // ================= epilogue =================
    const size_t BH = (size_t)Btot * H_DIM;
    #pragma unroll
    for (int mb = 0; mb < 2; mb++)
        #pragma unroll
        for (int nb = 0; nb < 8; nb++) {
            int colg = n0 + wn * 64 + nb * 8 + (lid & 3) * 2;
            float2 biv = *reinterpret_cast<const float2*>(bi + colg);
            #pragma unroll
            for (int jh = 0; jh < 2; jh++) {
                int rowl = wm * 32 + mb * 16 + (lid >> 2) + jh * 8;
                int rowg = m0 + rowl;
                int cp   = wn * 32 + nb * 4 + (lid & 3);
                uint32_t mq = *reinterpret_cast<const uint32_t*>(sm + SM_M + rowl * SM_MSTRIDE + cp * 4);
                float mg[2] = { (float)(mq & 0xFFFF) * (1.f / 65535.f),
                                (float)(mq >> 16)    * (1.f / 65535.f) };
                size_t o = (size_t)rowg * H_DIM + colg;
                float2 ct = *reinterpret_cast<const float2*>(c_t + o);
                float gr[2] = { d[mb][nb][jh*2+0] + biv.x, d[mb][nb][jh*2+1] + biv.y };
                float ctv[2] = { ct.x, ct.y };
                float hv[2], cv[2];
                #pragma unroll
                for (int e = 0; e < 2; e++) {
                    float g = fminf(fmaxf(gr[e], -30.f), 30.f);
                    float ex = __expf(-g);
                    float gate = __fdividef(1.f, 1.f + ex);
                    float e2 = ex * ex;
                    float thg = __fdividef(1.f - e2, 1.f + e2);        // tanh(g)
                    float c = gate * (ctv[e] + thg);
                    float cc = fminf(fmaxf(c, -15.f), 15.f);
                    float ec = __expf(-2.f * cc);
                    float cr = __fdividef(1.f - ec, 1.f + ec);         // tanh(c)
                    float cf = c - cr + cr * mg[e];
                    float cfc = fminf(fmaxf(cf, -15.f), 15.f);
                    float ef = __expf(-2.f * cfc);
                    float thf = __fdividef(1.f - ef, 1.f + ef);        // tanh(c_f)
                    hv[e] = thf * gate;
                    cv[e] = c;
                }
                float2 hvv = make_float2(hv[0], hv[1]);
                float2 cvv = make_float2(cv[0], cv[1]);
                *reinterpret_cast<float2*>(out + o)          = hvv;
                *reinterpret_cast<float2*>(out + BH + o)     = hvv;
                *reinterpret_cast<float2*>(out + 2 * BH + o) = cvv;
            }
        }
}

extern "C" void kernel_launch(void* const* d_in, const int* in_sizes, int n_in,
                              void* d_out, int out_size) {
    const float* inp   = (const float*)d_in[0];
    const float* media = (const float*)d_in[1];
    const float* h_t   = (const float*)d_in[2];
    const float* c_t   = (const float*)d_in[3];
    const float* Wi    = (const float*)d_in[4];
    const float* bi    = (const float*)d_in[5];
    const float* Wm    = (const float*)d_in[6];
    const float* bm    = (const float*)d_in[7];
    int B = in_sizes[0] / IN_DIM;

    cudaFuncSetAttribute(rlstm_kernel, cudaFuncAttributeMaxDynamicSharedMemorySize, SM_TOTAL);
    dim3 grid((B / TILE_M) * 2);
    rlstm_kernel<<<grid, THREADS, SM_TOTAL>>>(inp, media, h_t, c_t, Wi, bi, Wm, bm,
                                              (float*)d_out, B);
}

// round 7
// speedup vs baseline: 1.4192x; 1.4007x over previous
#include <cuda_runtime.h>
#include <cuda_fp16.h>
#include <cstdint>

#define IN_DIM   128
#define H_DIM    256
#define M_DIM    32
#define K_TOT    384
#define TILE_M   128
#define TILE_N   128
#define KC       32
#define NCHUNK   12
#define THREADS  256

// ---- SMEM layout (byte offsets) ----
// Each buffer: A_hi | A_lo | W (fp16), each 128 rows x 64B (8KB) = 24KB
#define OFF_AHI  0
#define OFF_ALO  8192
#define OFF_W    16384
#define BUF_SZ   24576
#define SM_BUF0  0
#define SM_BUF1  24576
#define SM_M     49152
#define SM_MSTRIDE 272
#define SM_TOTAL (SM_M + TILE_M*SM_MSTRIDE)   // 83968

static __device__ __forceinline__ uint32_t smem_u32(const void* p) {
    uint32_t a;
    asm("{ .reg .u64 t; cvta.to.shared.u64 t, %1; cvt.u32.u64 %0, t; }" : "=r"(a) : "l"(p));
    return a;
}
static __device__ __forceinline__ void ldsm4(uint32_t* r, uint32_t addr) {
    asm volatile("ldmatrix.sync.aligned.m8n8.x4.shared.b16 {%0,%1,%2,%3}, [%4];"
                 : "=r"(r[0]), "=r"(r[1]), "=r"(r[2]), "=r"(r[3]) : "r"(addr));
}
static __device__ __forceinline__ void mma_f16(float* d, const uint32_t* a, const uint32_t* b) {
    asm volatile("mma.sync.aligned.m16n8k16.row.col.f32.f16.f16.f32 "
                 "{%0,%1,%2,%3}, {%4,%5,%6,%7}, {%8,%9}, {%0,%1,%2,%3};"
                 : "+f"(d[0]), "+f"(d[1]), "+f"(d[2]), "+f"(d[3])
                 : "r"(a[0]), "r"(a[1]), "r"(a[2]), "r"(a[3]), "r"(b[0]), "r"(b[1]));
}

// fp32x4 -> fp16 hi (uint2) + fp16 residual (uint2)
static __device__ __forceinline__ void splitA(float4 v, uint2& hv, uint2& lv) {
    __half2 h01 = __float22half2_rn(make_float2(v.x, v.y));
    __half2 h23 = __float22half2_rn(make_float2(v.z, v.w));
    float2 f01 = __half22float2(h01);
    float2 f23 = __half22float2(h23);
    __half2 l01 = __float22half2_rn(make_float2(v.x - f01.x, v.y - f01.y));
    __half2 l23 = __float22half2_rn(make_float2(v.z - f23.x, v.w - f23.y));
    hv.x = *reinterpret_cast<uint32_t*>(&h01);
    hv.y = *reinterpret_cast<uint32_t*>(&h23);
    lv.x = *reinterpret_cast<uint32_t*>(&l01);
    lv.y = *reinterpret_cast<uint32_t*>(&l23);
}
// fp32x4 -> fp16x4 (uint2)
static __device__ __forceinline__ uint2 cvtW(float4 v) {
    __half2 h01 = __float22half2_rn(make_float2(v.x, v.y));
    __half2 h23 = __float22half2_rn(make_float2(v.z, v.w));
    uint2 o;
    o.x = *reinterpret_cast<uint32_t*>(&h01);
    o.y = *reinterpret_cast<uint32_t*>(&h23);
    return o;
}

__global__ __launch_bounds__(THREADS, 2)
void rlstm_kernel(const float* __restrict__ inp, const float* __restrict__ media,
                  const float* __restrict__ h_t, const float* __restrict__ c_t,
                  const float* __restrict__ Wi, const float* __restrict__ bi,
                  const float* __restrict__ Wm, const float* __restrict__ bm,
                  float* __restrict__ out, int Btot) {
    extern __shared__ char sm[];
    const uint32_t sb = smem_u32(sm);
    const int tid = threadIdx.x;
    const int lid = tid & 31;
    const int wid = tid >> 5;
    const int wm = wid & 3;          // warp row (4 x 32 = 128 M)
    const int wn = wid >> 2;         // warp col (2 x 64 = 128 N)
    const int m0 = (int)(blockIdx.x >> 1) * TILE_M;
    const int n0 = (int)(blockIdx.x & 1) * TILE_N;

    // ldmatrix per-lane components
    const int a_row0 = wm * 32 + (lid & 15);
    const int a_kh   = lid >> 4;
    const int b_row0 = wn * 64 + (lid & 7) + ((lid >> 4) << 3);
    const int b_kh   = (lid >> 3) & 1;

    // loader coords: 256 thr cover 32 rows x 32 cols (float4 units) per iter
    const int l_row = tid >> 3;            // +32 per iteration
    const int l_unit = tid & 7;
    const int l_k = l_unit * 4;
    const uint32_t l_boff = (uint32_t)(l_row * 64 + l_unit * 8);
    const uint32_t l_sw = l_boff ^ ((l_boff >> 3) & 0x30);

    float4 ra[4];                          // A prefetch only (16 regs)

    auto load_A = [&](int ch) {
        int kk = ch * KC + l_k;
        #pragma unroll
        for (int it = 0; it < 4; it++) {
            int row = l_row + it * 32;
            ra[it] = (kk < IN_DIM)
                ? *reinterpret_cast<const float4*>(inp + (size_t)(m0 + row) * IN_DIM + kk)
                : *reinterpret_cast<const float4*>(h_t + (size_t)(m0 + row) * H_DIM + (kk - IN_DIM));
        }
    };
    auto sts_A = [&](uint32_t buf) {
        #pragma unroll
        for (int it = 0; it < 4; it++) {
            uint2 hv, lv;
            splitA(ra[it], hv, lv);
            *reinterpret_cast<uint2*>(sm + buf + OFF_AHI + it * 2048 + l_sw) = hv;
            *reinterpret_cast<uint2*>(sm + buf + OFF_ALO + it * 2048 + l_sw) = lv;
        }
    };
    auto load_sts_W = [&](int ch, uint32_t buf) {
        int kk = ch * KC + l_k;
        #pragma unroll
        for (int it = 0; it < 4; it++) {
            int row = l_row + it * 32;
            float4 w = *reinterpret_cast<const float4*>(Wi + (size_t)(n0 + row) * K_TOT + kk);
            *reinterpret_cast<uint2*>(sm + buf + OFF_W + it * 2048 + l_sw) = cvtW(w);
        }
    };

    float d[2][8][4];
    auto zero_d = [&]() {
        #pragma unroll
        for (int mb = 0; mb < 2; mb++)
            #pragma unroll
            for (int nb = 0; nb < 8; nb++)
                #pragma unroll
                for (int j = 0; j < 4; j++) d[mb][nb][j] = 0.f;
    };

    auto run_chunk = [&](uint32_t buf) {
        const uint32_t bAH = sb + buf + OFF_AHI, bAL = sb + buf + OFF_ALO;
        const uint32_t bW  = sb + buf + OFF_W;
        #pragma unroll
        for (int ks = 0; ks < 2; ks++) {
            uint32_t afh[2][4], afl[2][4];
            #pragma unroll
            for (int mb = 0; mb < 2; mb++) {
                int row = a_row0 + mb * 16;
                uint32_t u = ((uint32_t)(ks * 2 + a_kh) ^ (uint32_t)((row >> 1) & 3)) << 4;
                ldsm4(afh[mb], bAH + (uint32_t)row * 64u + u);
                ldsm4(afl[mb], bAL + (uint32_t)row * 64u + u);
            }
            #pragma unroll
            for (int p = 0; p < 4; p++) {
                int row = b_row0 + p * 16;
                uint32_t u = ((uint32_t)(ks * 2 + b_kh) ^ (uint32_t)((row >> 1) & 3)) << 4;
                uint32_t t[4];
                ldsm4(t, bW + (uint32_t)row * 64u + u);
                mma_f16(d[0][2*p],   afh[0], t);     mma_f16(d[0][2*p+1], afh[0], t + 2);
                mma_f16(d[1][2*p],   afh[1], t);     mma_f16(d[1][2*p+1], afh[1], t + 2);
                mma_f16(d[0][2*p],   afl[0], t);     mma_f16(d[0][2*p+1], afl[0], t + 2);
                mma_f16(d[1][2*p],   afl[1], t);     mma_f16(d[1][2*p+1], afl[1], t + 2);
            }
        }
    };

    // ================= media prologue (chunk in buf0) =================
    {
        #pragma unroll
        for (int it = 0; it < 4; it++) {
            int row = l_row + it * 32;
            ra[it] = *reinterpret_cast<const float4*>(media + (size_t)(m0 + row) * M_DIM + l_k);
            float4 w = *reinterpret_cast<const float4*>(Wm + (size_t)(n0 + row) * M_DIM + l_k);
            *reinterpret_cast<uint2*>(sm + SM_BUF0 + OFF_W + it * 2048 + l_sw) = cvtW(w);
        }
        sts_A(SM_BUF0);
    }
    __syncthreads();
    zero_d();
    run_chunk(SM_BUF0);
    load_A(0);                    // prefetch main chunk 0 behind the sigmoid pass

    // sigmoid(media GEMM + bm) -> u16 fixed point in m-tile (same-thread read later)
    #pragma unroll
    for (int mb = 0; mb < 2; mb++)
        #pragma unroll
        for (int nb = 0; nb < 8; nb++) {
            int colg = n0 + wn * 64 + nb * 8 + (lid & 3) * 2;
            float2 bmv = *reinterpret_cast<const float2*>(bm + colg);
            #pragma unroll
            for (int jh = 0; jh < 2; jh++) {
                float x0 = fminf(fmaxf(d[mb][nb][jh*2+0] + bmv.x, -30.f), 30.f);
                float x1 = fminf(fmaxf(d[mb][nb][jh*2+1] + bmv.y, -30.f), 30.f);
                float g0 = __fdividef(1.f, 1.f + __expf(-x0));
                float g1 = __fdividef(1.f, 1.f + __expf(-x1));
                uint32_t q0 = __float2uint_rn(g0 * 65535.f);
                uint32_t q1 = __float2uint_rn(g1 * 65535.f);
                int rowl = wm * 32 + mb * 16 + (lid >> 2) + jh * 8;
                int cp   = wn * 32 + nb * 4 + (lid & 3);
                *reinterpret_cast<uint32_t*>(sm + SM_M + rowl * SM_MSTRIDE + cp * 4)
                    = q0 | (q1 << 16);
            }
        }

    __syncthreads();              // media GEMM reads of buf0 done everywhere
    sts_A(SM_BUF1);               // chunk 0 -> buf1
    load_sts_W(0, SM_BUF1);
    zero_d();
    __syncthreads();

    // ================= main pipeline: 12 chunks, double-buffered =================
    #pragma unroll 1
    for (int ch = 0; ch < NCHUNK; ch++) {
        uint32_t bufR = (ch & 1) ? SM_BUF0 : SM_BUF1;   // chunk ch lives here
        uint32_t bufW = (ch & 1) ? SM_BUF1 : SM_BUF0;   // chunk ch+1 goes here
        if (ch < NCHUNK - 1) load_A(ch + 1);            // DRAM-latency LDGs before MMAs
        run_chunk(bufR);
        if (ch < NCHUNK - 1) {
            sts_A(bufW);
            load_sts_W(ch + 1, bufW);                   // W is L2-resident
            __syncthreads();
        }
    }

    // ================= epilogue =================
    const size_t BH = (size_t)Btot * H_DIM;
    #pragma unroll
    for (int mb = 0; mb < 2; mb++)
        #pragma unroll
        for (int nb = 0; nb < 8; nb++) {
            int colg = n0 + wn * 64 + nb * 8 + (lid & 3) * 2;
            float2 biv = *reinterpret_cast<const float2*>(bi + colg);
            #pragma unroll
            for (int jh = 0; jh < 2; jh++) {
                int rowl = wm * 32 + mb * 16 + (lid >> 2) + jh * 8;
                int rowg = m0 + rowl;
                int cp   = wn * 32 + nb * 4 + (lid & 3);
                uint32_t mq = *reinterpret_cast<const uint32_t*>(sm + SM_M + rowl * SM_MSTRIDE + cp * 4);
                float mg[2] = { (float)(mq & 0xFFFF) * (1.f / 65535.f),
                                (float)(mq >> 16)    * (1.f / 65535.f) };
                size_t o = (size_t)rowg * H_DIM + colg;
                float2 ct = *reinterpret_cast<const float2*>(c_t + o);
                float gr[2] = { d[mb][nb][jh*2+0] + biv.x, d[mb][nb][jh*2+1] + biv.y };
                float ctv[2] = { ct.x, ct.y };
                float hv[2], cv[2];
                #pragma unroll
                for (int e = 0; e < 2; e++) {
                    float g = fminf(fmaxf(gr[e], -30.f), 30.f);
                    float ex = __expf(-g);
                    float gate = __fdividef(1.f, 1.f + ex);
                    float e2 = ex * ex;
                    float thg = __fdividef(1.f - e2, 1.f + e2);        // tanh(g)
                    float c = gate * (ctv[e] + thg);
                    float cc = fminf(fmaxf(c, -15.f), 15.f);
                    float ec = __expf(-2.f * cc);
                    float cr = __fdividef(1.f - ec, 1.f + ec);         // tanh(c)
                    float cf = c - cr + cr * mg[e];
                    float cfc = fminf(fmaxf(cf, -15.f), 15.f);
                    float ef = __expf(-2.f * cfc);
                    float thf = __fdividef(1.f - ef, 1.f + ef);        // tanh(c_f)
                    hv[e] = thf * gate;
                    cv[e] = c;
                }
                float2 hvv = make_float2(hv[0], hv[1]);
                float2 cvv = make_float2(cv[0], cv[1]);
                *reinterpret_cast<float2*>(out + o)          = hvv;
                *reinterpret_cast<float2*>(out + BH + o)     = hvv;
                *reinterpret_cast<float2*>(out + 2 * BH + o) = cvv;
            }
        }
}

extern "C" void kernel_launch(void* const* d_in, const int* in_sizes, int n_in,
                              void* d_out, int out_size) {
    const float* inp   = (const float*)d_in[0];
    const float* media = (const float*)d_in[1];
    const float* h_t   = (const float*)d_in[2];
    const float* c_t   = (const float*)d_in[3];
    const float* Wi    = (const float*)d_in[4];
    const float* bi    = (const float*)d_in[5];
    const float* Wm    = (const float*)d_in[6];
    const float* bm    = (const float*)d_in[7];
    int B = in_sizes[0] / IN_DIM;

    cudaFuncSetAttribute(rlstm_kernel, cudaFuncAttributeMaxDynamicSharedMemorySize, SM_TOTAL);
    dim3 grid((B / TILE_M) * 2);
    rlstm_kernel<<<grid, THREADS, SM_TOTAL>>>(inp, media, h_t, c_t, Wi, bi, Wm, bm,
                                              (float*)d_out, B);
}

// round 11
// speedup vs baseline: 1.5391x; 1.0845x over previous
#include <cuda_runtime.h>
#include <cstdint>

// Round 10 resubmit: identical to round-9 candidate (tf32 + cp.async, fixed
// separate A/W k-offsets). Previous round failed on infra (container), not kernel.

#define IN_DIM   128
#define H_DIM    256
#define M_DIM    32
#define K_TOT    384
#define TILE_M   128
#define TILE_N   128
#define KC       32            // fp32 per row per chunk = 128B rows
#define NCHUNK   12
#define THREADS  256

// ---- SMEM: two 32KB stage buffers (A 16KB | W 16KB), then m-gate tile ----
#define OFF_A    0
#define OFF_W    16384
#define SM_BUF0  0
#define SM_BUF1  32768
#define SM_M     65536
#define SM_MSTRIDE 272
#define SM_TOTAL (SM_M + TILE_M*SM_MSTRIDE)   // 100352

// compensation for tf32 truncation (2 operands): 1 + ~2*E[rel shrink]
#define COMP 1.000677f

static __device__ __forceinline__ uint32_t smem_u32(const void* p) {
    uint32_t a;
    asm("{ .reg .u64 t; cvta.to.shared.u64 t, %1; cvt.u32.u64 %0, t; }" : "=r"(a) : "l"(p));
    return a;
}
static __device__ __forceinline__ void ldsm4(uint32_t* r, uint32_t addr) {
    asm volatile("ldmatrix.sync.aligned.m8n8.x4.shared.b16 {%0,%1,%2,%3}, [%4];"
                 : "=r"(r[0]), "=r"(r[1]), "=r"(r[2]), "=r"(r[3]) : "r"(addr));
}
static __device__ __forceinline__ void mma_tf32(float* d, const uint32_t* a, const uint32_t* b) {
    asm volatile("mma.sync.aligned.m16n8k8.row.col.f32.tf32.tf32.f32 "
                 "{%0,%1,%2,%3}, {%4,%5,%6,%7}, {%8,%9}, {%0,%1,%2,%3};"
                 : "+f"(d[0]), "+f"(d[1]), "+f"(d[2]), "+f"(d[3])
                 : "r"(a[0]), "r"(a[1]), "r"(a[2]), "r"(a[3]), "r"(b[0]), "r"(b[1]));
}
#define CP16(dst, src) \
    asm volatile("cp.async.cg.shared.global [%0], [%1], 16;" \
                 :: "r"(dst), "l"(src) : "memory")
#define CPCOMMIT() asm volatile("cp.async.commit_group;" ::: "memory")
#define CPWAIT(n)  asm volatile("cp.async.wait_group %0;" :: "n"(n) : "memory")

__global__ __launch_bounds__(THREADS, 2)
void rlstm_kernel(const float* __restrict__ inp, const float* __restrict__ media,
                  const float* __restrict__ h_t, const float* __restrict__ c_t,
                  const float* __restrict__ Wi, const float* __restrict__ bi,
                  const float* __restrict__ Wm, const float* __restrict__ bm,
                  float* __restrict__ out, int Btot) {
    extern __shared__ char sm[];
    const uint32_t sb = smem_u32(sm);
    const int tid = threadIdx.x;
    const int lid = tid & 31;
    const int wid = tid >> 5;
    const int wm = wid & 3;          // 4 warp-rows x 32 = 128 M
    const int wn = wid >> 2;         // 2 warp-cols x 64 = 128 N
    const int m0 = (int)(blockIdx.x >> 1) * TILE_M;
    const int n0 = (int)(blockIdx.x & 1) * TILE_N;

    // ---- cp.async loader coords: 256 thr x 16B = 4KB/pass; 4 passes per 16KB tile
    const int l_row  = tid >> 3;           // +32 per pass; (row & 7) invariant
    const int l_unit = tid & 7;
    const uint32_t l_su = (uint32_t)(l_unit ^ (l_row & 7)) << 4;   // swizzled 16B unit

    // ---- ldmatrix per-lane components (tf32 via b16 pair trick) ----
    const int ai = lid & 7;
    const int atile = lid >> 3;
    const int arow_off = (atile & 1) * 8 + ai;       // + wm*32 + mb*16
    const int aub = atile >> 1;
    const int wtile = lid >> 3;
    const int wrow_off = (wtile >> 1) * 8 + ai;      // + wn*64 + nb2*16
    const int wub = wtile & 1;

    // NOTE: separate k-offsets for A and W — they differ once A switches to h_t.
    auto cp_chunk = [&](uint32_t buf, const float* asrc, int astride, int akk,
                        const float* wsrc, int wstride, int wkk) {
        #pragma unroll
        for (int it = 0; it < 4; it++) {
            int row = l_row + it * 32;
            uint32_t dst = sb + buf + (uint32_t)row * 128u + l_su;
            CP16(dst + OFF_A, asrc + (size_t)row * astride + akk + l_unit * 4);
            CP16(dst + OFF_W, wsrc + (size_t)row * wstride + wkk + l_unit * 4);
        }
        CPCOMMIT();
    };
    auto cp_main = [&](int ch) {
        uint32_t buf = (ch & 1) ? SM_BUF0 : SM_BUF1;     // chunk ch lands here
        if (ch < 4)
            cp_chunk(buf, inp + (size_t)m0 * IN_DIM, IN_DIM, ch * KC,
                          Wi + (size_t)n0 * K_TOT, K_TOT, ch * KC);
        else
            cp_chunk(buf, h_t + (size_t)m0 * H_DIM, H_DIM, (ch - 4) * KC,
                          Wi + (size_t)n0 * K_TOT, K_TOT, ch * KC);
    };

    float d[2][8][4];
    auto zero_d = [&]() {
        #pragma unroll
        for (int mb = 0; mb < 2; mb++)
            #pragma unroll
            for (int nb = 0; nb < 8; nb++)
                #pragma unroll
                for (int j = 0; j < 4; j++) d[mb][nb][j] = 0.f;
    };

    auto run_chunk = [&](uint32_t buf) {
        const uint32_t bA = sb + buf + OFF_A;
        const uint32_t bW = sb + buf + OFF_W;
        #pragma unroll
        for (int s = 0; s < 4; s++) {            // 4 k8-steps = KC 32
            uint32_t a[2][4];
            #pragma unroll
            for (int mb = 0; mb < 2; mb++) {
                int row = wm * 32 + mb * 16 + arow_off;
                uint32_t u = (uint32_t)((2 * s + aub) ^ ai) << 4;
                ldsm4(a[mb], bA + (uint32_t)row * 128u + u);
            }
            #pragma unroll
            for (int nb2 = 0; nb2 < 4; nb2++) {
                int row = wn * 64 + nb2 * 16 + wrow_off;
                uint32_t u = (uint32_t)((2 * s + wub) ^ ai) << 4;
                uint32_t t[4];
                ldsm4(t, bW + (uint32_t)row * 128u + u);
                mma_tf32(d[0][2*nb2],   a[0], t);
                mma_tf32(d[0][2*nb2+1], a[0], t + 2);
                mma_tf32(d[1][2*nb2],   a[1], t);
                mma_tf32(d[1][2*nb2+1], a[1], t + 2);
            }
        }
    };

    // ================= prologue: media chunk -> buf0, main chunk0 -> buf1 =================
    cp_chunk(SM_BUF0, media + (size_t)m0 * M_DIM, M_DIM, 0,
                      Wm + (size_t)n0 * M_DIM, M_DIM, 0);           // group: media
    cp_main(0);                                                      // group: chunk0
    CPWAIT(1);
    __syncthreads();
    zero_d();
    run_chunk(SM_BUF0);                    // media GEMM (K=32)

    // sigmoid(media + bm) -> u16 fixed point in m-tile
    #pragma unroll
    for (int mb = 0; mb < 2; mb++)
        #pragma unroll
        for (int nb = 0; nb < 8; nb++) {
            int colg = n0 + wn * 64 + nb * 8 + (lid & 3) * 2;
            float2 bmv = *reinterpret_cast<const float2*>(bm + colg);
            #pragma unroll
            for (int jh = 0; jh < 2; jh++) {
                float x0 = fminf(fmaxf(d[mb][nb][jh*2+0] * COMP + bmv.x, -30.f), 30.f);
                float x1 = fminf(fmaxf(d[mb][nb][jh*2+1] * COMP + bmv.y, -30.f), 30.f);
                float g0 = __fdividef(1.f, 1.f + __expf(-x0));
                float g1 = __fdividef(1.f, 1.f + __expf(-x1));
                uint32_t q0 = __float2uint_rn(g0 * 65535.f);
                uint32_t q1 = __float2uint_rn(g1 * 65535.f);
                int rowl = wm * 32 + mb * 16 + (lid >> 2) + jh * 8;
                int cp   = wn * 32 + nb * 4 + (lid & 3);
                *reinterpret_cast<uint32_t*>(sm + SM_M + rowl * SM_MSTRIDE + cp * 4)
                    = q0 | (q1 << 16);
            }
        }
    __syncthreads();               // everyone done reading buf0
    cp_main(1);                    // chunk1 -> buf0
    zero_d();

    // ================= mainloop: 12 chunks, 2-stage cp.async =================
    #pragma unroll 1
    for (int ch = 0; ch < NCHUNK; ch++) {
        uint32_t bufR = (ch & 1) ? SM_BUF0 : SM_BUF1;
        if (ch < NCHUNK - 1) { CPWAIT(1); } else { CPWAIT(0); }
        __syncthreads();
        run_chunk(bufR);
        if (ch < NCHUNK - 2) {
            __syncthreads();       // all readers done with bufR
            cp_main(ch + 2);       // overwrite bufR with chunk ch+2
        }
    }

    // ================= epilogue =================
    const size_t BH = (size_t)Btot * H_DIM;
    #pragma unroll
    for (int mb = 0; mb < 2; mb++)
        #pragma unroll
        for (int nb = 0; nb < 8; nb++) {
            int colg = n0 + wn * 64 + nb * 8 + (lid & 3) * 2;
            float2 biv = *reinterpret_cast<const float2*>(bi + colg);
            #pragma unroll
            for (int jh = 0; jh < 2; jh++) {
                int rowl = wm * 32 + mb * 16 + (lid >> 2) + jh * 8;
                int rowg = m0 + rowl;
                int cp   = wn * 32 + nb * 4 + (lid & 3);
                uint32_t mq = *reinterpret_cast<const uint32_t*>(sm + SM_M + rowl * SM_MSTRIDE + cp * 4);
                float mg[2] = { (float)(mq & 0xFFFF) * (1.f / 65535.f),
                                (float)(mq >> 16)    * (1.f / 65535.f) };
                size_t o = (size_t)rowg * H_DIM + colg;
                float2 ct = *reinterpret_cast<const float2*>(c_t + o);
                float gr[2] = { d[mb][nb][jh*2+0] * COMP + biv.x,
                                d[mb][nb][jh*2+1] * COMP + biv.y };
                float ctv[2] = { ct.x, ct.y };
                float hv[2], cv[2];
                #pragma unroll
                for (int e = 0; e < 2; e++) {
                    float g = fminf(fmaxf(gr[e], -30.f), 30.f);
                    float ex = __expf(-g);
                    float gate = __fdividef(1.f, 1.f + ex);
                    float e2 = ex * ex;
                    float thg = __fdividef(1.f - e2, 1.f + e2);        // tanh(g)
                    float c = gate * (ctv[e] + thg);
                    float cc = fminf(fmaxf(c, -15.f), 15.f);
                    float ec = __expf(-2.f * cc);
                    float cr = __fdividef(1.f - ec, 1.f + ec);         // tanh(c)
                    float cf = c - cr + cr * mg[e];
                    float cfc = fminf(fmaxf(cf, -15.f), 15.f);
                    float ef = __expf(-2.f * cfc);
                    float thf = __fdividef(1.f - ef, 1.f + ef);        // tanh(c_f)
                    hv[e] = thf * gate;
                    cv[e] = c;
                }
                float2 hvv = make_float2(hv[0], hv[1]);
                float2 cvv = make_float2(cv[0], cv[1]);
                *reinterpret_cast<float2*>(out + o)          = hvv;
                *reinterpret_cast<float2*>(out + BH + o)     = hvv;
                *reinterpret_cast<float2*>(out + 2 * BH + o) = cvv;
            }
        }
}

extern "C" void kernel_launch(void* const* d_in, const int* in_sizes, int n_in,
                              void* d_out, int out_size) {
    const float* inp   = (const float*)d_in[0];
    const float* media = (const float*)d_in[1];
    const float* h_t   = (const float*)d_in[2];
    const float* c_t   = (const float*)d_in[3];
    const float* Wi    = (const float*)d_in[4];
    const float* bi    = (const float*)d_in[5];
    const float* Wm    = (const float*)d_in[6];
    const float* bm    = (const float*)d_in[7];
    int B = in_sizes[0] / IN_DIM;

    cudaFuncSetAttribute(rlstm_kernel, cudaFuncAttributeMaxDynamicSharedMemorySize, SM_TOTAL);
    dim3 grid((B / TILE_M) * 2);
    rlstm_kernel<<<grid, THREADS, SM_TOTAL>>>(inp, media, h_t, c_t, Wi, bi, Wm, bm,
                                              (float*)d_out, B);
}